// round 14
// baseline (speedup 1.0000x reference)
#include <cuda_runtime.h>
#include <cuda_bf16.h>
#include <cstdint>

#define BATCH 16
#define CCH   512
#define CI    256
#define NPIX  4096
#define FSPLIT 4

// ---------------- scratch (device globals; no allocation allowed) ----------------
static const size_t XT_SZ  = (size_t)BATCH * NPIX * CCH;   // per level
static const size_t TP_SZ  = (size_t)BATCH * 512 * NPIX;
static const size_t GT_SZ  = (size_t)BATCH * NPIX * CI;
static const size_t F_SZ   = (size_t)BATCH * CI * CI;
static const size_t YT_SZ  = (size_t)BATCH * NPIX * CI;

__device__ __nv_bfloat16 d_xt [2][(size_t)BATCH * NPIX * CCH];   // 134 MB
__device__ __nv_bfloat16 d_wtp[2][512 * 512];
__device__ __nv_bfloat16 d_gw [2][CI * CCH];
__device__ __nv_bfloat16 d_ww [2][CCH * CI];
__device__ __nv_bfloat16 d_tp [2][(size_t)BATCH * 512 * NPIX];   // 134 MB
__device__ __nv_bfloat16 d_gt [2][(size_t)BATCH * NPIX * CI];    // 67 MB
__device__ float         d_fpart[(size_t)FSPLIT * BATCH * CI * CI]; // 16.8 MB
__device__ __nv_bfloat16 d_fsm[2][(size_t)BATCH * CI * CI];
__device__ __nv_bfloat16 d_yt [2][(size_t)BATCH * NPIX * CI];    // 67 MB
__device__ float         d_z[(size_t)BATCH * CCH * NPIX];        // 134 MB
__device__ float         d_stats[2 * CCH];                       // raw partials
__device__ float         d_tpb[512];

// ---------------- helpers (arch-portable PTX only: sm_80+) ----------------
__device__ __forceinline__ uint32_t smem_u32(const void* p) {
    uint32_t a;
    asm("{ .reg .u64 t; cvta.to.shared.u64 t, %1; cvt.u32.u64 %0, t; }" : "=r"(a) : "l"(p));
    return a;
}

__device__ __forceinline__ void cpasync16(uint32_t dst, const void* src) {
    asm volatile("cp.async.cg.shared.global [%0], [%1], 16;" :: "r"(dst), "l"(src));
}
#define CP_COMMIT() asm volatile("cp.async.commit_group;" ::: "memory")

__device__ __forceinline__ void ldsm4(uint32_t addr, uint32_t& r0, uint32_t& r1,
                                      uint32_t& r2, uint32_t& r3) {
    asm volatile("ldmatrix.sync.aligned.m8n8.x4.shared.b16 {%0,%1,%2,%3}, [%4];"
                 : "=r"(r0), "=r"(r1), "=r"(r2), "=r"(r3) : "r"(addr));
}
__device__ __forceinline__ void mma16816(float* c, const uint32_t* a, uint32_t b0, uint32_t b1) {
    asm volatile(
        "mma.sync.aligned.m16n8k16.row.col.f32.bf16.bf16.f32 "
        "{%0,%1,%2,%3}, {%4,%5,%6,%7}, {%8,%9}, {%0,%1,%2,%3};"
        : "+f"(c[0]), "+f"(c[1]), "+f"(c[2]), "+f"(c[3])
        : "r"(a[0]), "r"(a[1]), "r"(a[2]), "r"(a[3]), "r"(b0), "r"(b1));
}

// =====================================================================
// NT GEMM on tensor cores (mma.sync bf16, fp32 acc), 2-level split inputs:
//   D[M,N] = A0*B0^T + A0*B1^T + A1*B0^T    (ll term dropped, ~2^-18)
// Shapes are TEMPLATE params. A,B: K-major (ld = Kv). CTA tile 64x128,
// 128 threads (4 warps, warp tile 32x64). K-chunk 32 (64B rows, SW64),
// 2-stage cp.async pipeline, ONE __syncthreads per chunk,
// loads for i+1 issued mid-compute. 49KB smem -> 4 CTAs/SM.
// MODE: 0 = fp32 out (optional fused stats atomics), 1 = hi/lo bf16 out.
// grid = (Nv/128, Mv/64, batch*NSPLIT)
// =====================================================================
template <int MODE, int Mv, int Nv, int Kv, int NSPLIT>
__global__ __launch_bounds__(128, 4) void mma_nt(
    const __nv_bfloat16* __restrict__ a0, const __nv_bfloat16* __restrict__ a1,
    const __nv_bfloat16* __restrict__ b0, const __nv_bfloat16* __restrict__ b1,
    float* __restrict__ cf,
    __nv_bfloat16* __restrict__ c0, __nv_bfloat16* __restrict__ c1,
    const float* __restrict__ biasRow, const float* __restrict__ biasCol,
    float* __restrict__ statsPart,
    long long sA, long long sB, long long sC)
{
    constexpr int stageBytes = 24576;       // A0 4K | A1 4K | B0 8K | B1 8K
    constexpr int Ksub = Kv / NSPLIT;
    constexpr int nk = Ksub / 32;

    extern __shared__ char smraw[];
    const uint32_t smem_base = (smem_u32(smraw) + 1023u) & ~1023u;

    const int tid = threadIdx.x;
    const int wid = tid >> 5, lid = tid & 31;
    const int warpM = (wid & 1) * 32;       // 2 warps over M (64 rows)
    const int warpN = (wid >> 1) * 64;      // 2 warps over N (128 cols)

    const int bz = blockIdx.z;
    const int b  = bz / NSPLIT, sp = bz % NSPLIT;
    const int k0base = sp * Ksub;
    const int mBase = blockIdx.y * 64;
    const int nBase = blockIdx.x * 128;

    // ---- precomputed cp.async addressing (prologue only) ----
    const int row0 = tid >> 2;              // 0..31
    const int segE = (tid & 3) * 8;
    const __nv_bfloat16* srcA0 = a0 + (size_t)b * sA + (size_t)(mBase + row0) * Kv + k0base + segE;
    const __nv_bfloat16* srcA1 = a1 + (size_t)b * sA + (size_t)(mBase + row0) * Kv + k0base + segE;
    const __nv_bfloat16* srcB0 = b0 + (size_t)b * sB + (size_t)(nBase + row0) * Kv + k0base + segE;
    const __nv_bfloat16* srcB1 = b1 + (size_t)b * sB + (size_t)(nBase + row0) * Kv + k0base + segE;
    uint32_t dstO[4];                       // swizzled dst offsets, tile-local
    #pragma unroll
    for (int c = 0; c < 4; c++) {
        const int row = row0 + 32 * c;
        const uint32_t o = row * 64 + (tid & 3) * 16;
        dstO[c] = o ^ ((row & 6) * 8);      // SW64 swizzle, precomputed
    }

    auto loadChunk = [&](int ci, uint32_t sb) {
        const __nv_bfloat16* s0 = srcA0 + (size_t)ci * 32;
        const __nv_bfloat16* s1 = srcA1 + (size_t)ci * 32;
        const __nv_bfloat16* s2 = srcB0 + (size_t)ci * 32;
        const __nv_bfloat16* s3 = srcB1 + (size_t)ci * 32;
        #pragma unroll
        for (int c = 0; c < 2; c++) {       // A tiles: 64 rows
            cpasync16(sb + dstO[c],         s0 + (size_t)c * 32 * Kv);
            cpasync16(sb + 4096 + dstO[c],  s1 + (size_t)c * 32 * Kv);
        }
        #pragma unroll
        for (int c = 0; c < 4; c++) {       // B tiles: 128 rows
            cpasync16(sb + 8192 + dstO[c],  s2 + (size_t)c * 32 * Kv);
            cpasync16(sb + 16384 + dstO[c], s3 + (size_t)c * 32 * Kv);
        }
    };

    float acc[2][8][4];
    #pragma unroll
    for (int i = 0; i < 2; i++)
        #pragma unroll
        for (int j = 0; j < 8; j++)
            #pragma unroll
            for (int k = 0; k < 4; k++) acc[i][j][k] = 0.f;

    loadChunk(0, smem_base); CP_COMMIT();

    const int lRow = lid & 15;
    const uint32_t colH = ((lid >> 4) & 1) * 16;

    // precomputed FULL ldsm offsets (stage-relative): 1 ADD per LDSM at use
    uint32_t offA[2][2], offB[2][4];        // [ks][site]
    #pragma unroll
    for (int mi = 0; mi < 2; mi++) {
        const int row = warpM + 16 * mi + lRow;
        const uint32_t ba = row * 64, xr = (row & 6) * 8;
        offA[0][mi] = ba + (colH ^ xr);
        offA[1][mi] = ba + ((32 + colH) ^ xr);
    }
    #pragma unroll
    for (int nj = 0; nj < 4; nj++) {
        const int row = warpN + 16 * nj + lRow;
        const uint32_t ba = row * 64, xr = (row & 6) * 8;
        offB[0][nj] = ba + (colH ^ xr);
        offB[1][nj] = ba + ((32 + colH) ^ xr);
    }

// One ks-step: product order A0B0 -> (load fb1) A0B1 -> (load fa1) A1B0.
// Peak live frags: fa0(8)+fb0(16)+fb1(16)=40 regs.
#define COMPUTE_KS(KS)                                                          \
    {                                                                           \
        uint32_t fa0[2][4], fb0[4][4];                                          \
        _Pragma("unroll")                                                       \
        for (int mi = 0; mi < 2; mi++)                                          \
            ldsm4(A0b + offA[KS][mi],                                           \
                  fa0[mi][0], fa0[mi][1], fa0[mi][2], fa0[mi][3]);              \
        _Pragma("unroll")                                                       \
        for (int nj = 0; nj < 4; nj++)                                          \
            ldsm4(B0b + offB[KS][nj],                                           \
                  fb0[nj][0], fb0[nj][1], fb0[nj][2], fb0[nj][3]);              \
        _Pragma("unroll")                                                       \
        for (int mi = 0; mi < 2; mi++)                                          \
            _Pragma("unroll")                                                   \
            for (int jn = 0; jn < 8; jn++)                                      \
                mma16816(acc[mi][jn], fa0[mi],                                  \
                         fb0[jn >> 1][jn & 1], fb0[jn >> 1][2 + (jn & 1)]);     \
        {                                                                       \
            uint32_t fb1[4][4];                                                 \
            _Pragma("unroll")                                                   \
            for (int nj = 0; nj < 4; nj++)                                      \
                ldsm4(B1b + offB[KS][nj],                                       \
                      fb1[nj][0], fb1[nj][1], fb1[nj][2], fb1[nj][3]);          \
            _Pragma("unroll")                                                   \
            for (int mi = 0; mi < 2; mi++)                                      \
                _Pragma("unroll")                                               \
                for (int jn = 0; jn < 8; jn++)                                  \
                    mma16816(acc[mi][jn], fa0[mi],                              \
                             fb1[jn >> 1][jn & 1], fb1[jn >> 1][2 + (jn & 1)]); \
        }                                                                       \
        {                                                                       \
            uint32_t fa1[2][4];                                                 \
            _Pragma("unroll")                                                   \
            for (int mi = 0; mi < 2; mi++)                                      \
                ldsm4(A1b + offA[KS][mi],                                       \
                      fa1[mi][0], fa1[mi][1], fa1[mi][2], fa1[mi][3]);          \
            _Pragma("unroll")                                                   \
            for (int mi = 0; mi < 2; mi++)                                      \
                _Pragma("unroll")                                               \
                for (int jn = 0; jn < 8; jn++)                                  \
                    mma16816(acc[mi][jn], fa1[mi],                              \
                             fb0[jn >> 1][jn & 1], fb0[jn >> 1][2 + (jn & 1)]); \
        }                                                                       \
    }

    #pragma unroll 1
    for (int i = 0; i < nk; i++) {
        const uint32_t sb = smem_base + (i & 1) * stageBytes;
        asm volatile("cp.async.wait_group 0;" ::: "memory");   // chunk i arrived
        __syncthreads();   // + all warps done reading the OTHER buffer (chunk i-1)

        const uint32_t A0b = sb, A1b = sb + 4096;
        const uint32_t B0b = sb + 8192, B1b = sb + 16384;

        COMPUTE_KS(0);
        if (i + 1 < nk) {
            loadChunk(i + 1, smem_base + ((i + 1) & 1) * stageBytes);
            CP_COMMIT();
        }
        COMPUTE_KS(1);
    }
#undef COMPUTE_KS

    // ---- epilogue ----
    const int gr = lid >> 2;            // 0..7
    const int gc = (lid & 3) * 2;       // 0,2,4,6
    const size_t cOff = (size_t)bz * sC;

    #pragma unroll
    for (int mi = 0; mi < 2; mi++) {
        const int row0e = mBase + warpM + 16 * mi + gr;
        const int row1e = row0e + 8;
        const float br0 = biasRow ? biasRow[row0e] : 0.f;
        const float br1 = biasRow ? biasRow[row1e] : 0.f;
        float s0 = 0.f, q0 = 0.f, s1 = 0.f, q1 = 0.f;
        #pragma unroll
        for (int jn = 0; jn < 8; jn++) {
            const int col = nBase + warpN + 8 * jn + gc;
            float v00 = acc[mi][jn][0] + br0;
            float v01 = acc[mi][jn][1] + br0;
            float v10 = acc[mi][jn][2] + br1;
            float v11 = acc[mi][jn][3] + br1;
            if (biasCol) {
                const float bc0 = biasCol[col], bc1 = biasCol[col + 1];
                v00 += bc0; v01 += bc1; v10 += bc0; v11 += bc1;
            }
            const size_t base0 = cOff + (size_t)row0e * Nv + col;
            const size_t base1 = cOff + (size_t)row1e * Nv + col;
            if (MODE == 0) {
                *(float2*)(cf + base0) = make_float2(v00, v01);
                *(float2*)(cf + base1) = make_float2(v10, v11);
                if (statsPart) {
                    s0 += v00 + v01; q0 += v00 * v00 + v01 * v01;
                    s1 += v10 + v11; q1 += v10 * v10 + v11 * v11;
                }
            } else {
                float vv[2][2] = {{v00, v01}, {v10, v11}};
                const size_t bb[2] = {base0, base1};
                #pragma unroll
                for (int r = 0; r < 2; r++) {
                    __nv_bfloat16 h0 = __float2bfloat16(vv[r][0]);
                    __nv_bfloat16 h1 = __float2bfloat16(vv[r][1]);
                    float r0 = vv[r][0] - __bfloat162float(h0);
                    float r1 = vv[r][1] - __bfloat162float(h1);
                    __nv_bfloat162 th; th.x = h0; th.y = h1;
                    __nv_bfloat162 tl;
                    tl.x = __float2bfloat16(r0); tl.y = __float2bfloat16(r1);
                    *(__nv_bfloat162*)(c0 + bb[r]) = th;
                    *(__nv_bfloat162*)(c1 + bb[r]) = tl;
                }
            }
        }
        if (MODE == 0 && statsPart) {
            #pragma unroll
            for (int o = 1; o < 4; o <<= 1) {
                s0 += __shfl_xor_sync(0xFFFFFFFFu, s0, o);
                q0 += __shfl_xor_sync(0xFFFFFFFFu, q0, o);
                s1 += __shfl_xor_sync(0xFFFFFFFFu, s1, o);
                q1 += __shfl_xor_sync(0xFFFFFFFFu, q1, o);
            }
            if ((lid & 3) == 0) {
                atomicAdd(&statsPart[row0e], s0);
                atomicAdd(&statsPart[CCH + row0e], q0);
                atomicAdd(&statsPart[row1e], s1);
                atomicAdd(&statsPart[CCH + row1e], q1);
            }
        }
    }
}

// =====================================================================
// prep: all four weight splits + bias stack + stats zero (ONE launch)
// =====================================================================
__global__ void prep_splits(
    const float* __restrict__ th_w, const float* __restrict__ ph_w,
    const float* __restrict__ g_w,  const float* __restrict__ W_w,
    __nv_bfloat16* __restrict__ wtp0, __nv_bfloat16* __restrict__ wtp1,
    __nv_bfloat16* __restrict__ gw0,  __nv_bfloat16* __restrict__ gw1,
    __nv_bfloat16* __restrict__ ww0,  __nv_bfloat16* __restrict__ ww1,
    const float* __restrict__ th_b, const float* __restrict__ ph_b,
    float* __restrict__ tpb, float* __restrict__ stats)
{
    const int i = blockIdx.x * 256 + threadIdx.x;   // 0 .. 4*131072-1
    const int arr = i >> 17;
    const int off = i & 131071;
    const float* src;
    __nv_bfloat16 *dh, *dl;
    switch (arr) {
        case 0:  src = th_w; dh = wtp0;          dl = wtp1;          break;
        case 1:  src = ph_w; dh = wtp0 + 131072; dl = wtp1 + 131072; break;
        case 2:  src = g_w;  dh = gw0;           dl = gw1;           break;
        default: src = W_w;  dh = ww0;           dl = ww1;           break;
    }
    const float v = src[off];
    const __nv_bfloat16 hh = __float2bfloat16(v);
    dh[off] = hh;
    dl[off] = __float2bfloat16(v - __bfloat162float(hh));

    if (i < 512)  tpb[i]  = (i < 256) ? th_b[i] : ph_b[i - 256];
    if (i < 1024) stats[i] = 0.f;
}

// =====================================================================
// transpose + 2-level split of x: 32n x 64c tiles, full-width bf16x2 stores
// =====================================================================
__global__ void transpose_split2(const float* __restrict__ x,
                                 __nv_bfloat16* __restrict__ h,
                                 __nv_bfloat16* __restrict__ l)
{
    __shared__ float t[64][33];
    const int b = blockIdx.z;
    const int n0 = blockIdx.x * 32, c0 = blockIdx.y * 64;
    const float* xb = x + (size_t)b * CCH * NPIX;
    // load 64 channel-rows x 32 pixels (coalesced 128B per row)
    #pragma unroll
    for (int k = 0; k < 8; k++) {
        const int cl = threadIdx.y + k * 8;
        t[cl][threadIdx.x] = xb[(size_t)(c0 + cl) * NPIX + n0 + threadIdx.x];
    }
    __syncthreads();
    // write 32 pixel-rows x 64 channels; each thread stores one bf16x2 per array
    const size_t ob = (size_t)b * NPIX * CCH;
    #pragma unroll
    for (int k = 0; k < 4; k++) {
        const int nl = threadIdx.y + k * 8;
        const float v0 = t[2 * threadIdx.x][nl];
        const float v1 = t[2 * threadIdx.x + 1][nl];
        const __nv_bfloat16 h0 = __float2bfloat16(v0);
        const __nv_bfloat16 h1 = __float2bfloat16(v1);
        __nv_bfloat162 th; th.x = h0; th.y = h1;
        __nv_bfloat162 tl;
        tl.x = __float2bfloat16(v0 - __bfloat162float(h0));
        tl.y = __float2bfloat16(v1 - __bfloat162float(h1));
        const size_t idx = ob + (size_t)(n0 + nl) * CCH + c0 + 2 * threadIdx.x;
        *(__nv_bfloat162*)(h + idx) = th;
        *(__nv_bfloat162*)(l + idx) = tl;
    }
}

__global__ __launch_bounds__(256) void softmax_split(
    const float* __restrict__ fp, __nv_bfloat16* __restrict__ h, __nv_bfloat16* __restrict__ l)
{
    const int row = blockIdx.x;        // b*256 + c
    const int b = row >> 8, c = row & 255;
    const int d = threadIdx.x;
    float v = 0.f;
    #pragma unroll
    for (int s = 0; s < FSPLIT; s++)
        v += fp[((size_t)(b * FSPLIT + s)) * (CI * CI) + c * CI + d];
    __shared__ float red[256];
    red[d] = v; __syncthreads();
    for (int o = 128; o > 0; o >>= 1) {
        if (d < o) red[d] = fmaxf(red[d], red[d + o]);
        __syncthreads();
    }
    const float mx = red[0];
    __syncthreads();
    const float e = __expf(v - mx);
    red[d] = e; __syncthreads();
    for (int o = 128; o > 0; o >>= 1) {
        if (d < o) red[d] += red[d + o];
        __syncthreads();
    }
    const float p = e / red[0];
    const size_t idx = (size_t)row * CI + d;
    __nv_bfloat16 hh = __float2bfloat16(p);
    h[idx] = hh; l[idx] = __float2bfloat16(p - __bfloat162float(hh));
}

// =====================================================================
// BN (finalize folded in) + residual
// =====================================================================
__global__ __launch_bounds__(256) void bn_residual(
    const float* __restrict__ z, const float* __restrict__ x,
    const float* __restrict__ gamma, const float* __restrict__ beta,
    const float* __restrict__ stats, float* __restrict__ out)
{
    const size_t i = (size_t)blockIdx.x * blockDim.x + threadIdx.x;
    const int c = (int)((i >> 10) & (CCH - 1));
    const float cnt = (float)(BATCH * NPIX);
    const float m = stats[c] / cnt;
    const float var = stats[CCH + c] / cnt - m * m;
    const float r = rsqrtf(var + 1e-5f);
    const float g = gamma[c], bb = beta[c];
    const float4 zv = ((const float4*)z)[i];
    const float4 xv = ((const float4*)x)[i];
    float4 o;
    o.x = (zv.x - m) * r * g + bb + xv.x;
    o.y = (zv.y - m) * r * g + bb + xv.y;
    o.z = (zv.z - m) * r * g + bb + xv.z;
    o.w = (zv.w - m) * r * g + bb + xv.w;
    ((float4*)out)[i] = o;
}

// =====================================================================
// launch
// =====================================================================
extern "C" void kernel_launch(void* const* d_in, const int* in_sizes, int n_in,
                              void* d_out, int out_size)
{
    (void)in_sizes; (void)n_in; (void)out_size;
    const float* x     = (const float*)d_in[0];
    const float* g_w   = (const float*)d_in[1];
    const float* g_b   = (const float*)d_in[2];
    const float* th_w  = (const float*)d_in[3];
    const float* th_b  = (const float*)d_in[4];
    const float* ph_w  = (const float*)d_in[5];
    const float* ph_b  = (const float*)d_in[6];
    const float* W_w   = (const float*)d_in[7];
    const float* gamma = (const float*)d_in[9];
    const float* beta  = (const float*)d_in[10];
    float* out = (float*)d_out;

    __nv_bfloat16 *xt, *wtp, *gw, *ww, *tp, *gt, *fsm, *yt;
    float *fpart, *z, *stats, *tpb;
    cudaGetSymbolAddress((void**)&xt,    d_xt);
    cudaGetSymbolAddress((void**)&wtp,   d_wtp);
    cudaGetSymbolAddress((void**)&gw,    d_gw);
    cudaGetSymbolAddress((void**)&ww,    d_ww);
    cudaGetSymbolAddress((void**)&tp,    d_tp);
    cudaGetSymbolAddress((void**)&gt,    d_gt);
    cudaGetSymbolAddress((void**)&fpart, d_fpart);
    cudaGetSymbolAddress((void**)&fsm,   d_fsm);
    cudaGetSymbolAddress((void**)&yt,    d_yt);
    cudaGetSymbolAddress((void**)&z,     d_z);
    cudaGetSymbolAddress((void**)&stats, d_stats);
    cudaGetSymbolAddress((void**)&tpb,   d_tpb);

    __nv_bfloat16 *xt0 = xt, *xt1 = xt + XT_SZ;
    __nv_bfloat16 *wtp0 = wtp, *wtp1 = wtp + 512 * 512;
    __nv_bfloat16 *gw0 = gw, *gw1 = gw + CI * CCH;
    __nv_bfloat16 *ww0 = ww, *ww1 = ww + CCH * CI;
    __nv_bfloat16 *tp0 = tp, *tp1 = tp + TP_SZ;
    __nv_bfloat16 *gt0 = gt, *gt1 = gt + GT_SZ;
    __nv_bfloat16 *fs0 = fsm, *fs1 = fsm + F_SZ;
    __nv_bfloat16 *yt0 = yt, *yt1 = yt + YT_SZ;

    const int SMEM = 2 * 24576 + 1024;   // 2-stage, K-chunk 32: 50176 B -> 4 CTAs/SM

    auto* k1a = mma_nt<1, 512,  NPIX, CCH, 1>;
    auto* k1b = mma_nt<1, NPIX, CI,   CCH, 1>;
    auto* k2  = mma_nt<0, CI,   CI,   NPIX, FSPLIT>;
    auto* k3  = mma_nt<1, NPIX, CI,   CI,  1>;
    auto* k4  = mma_nt<0, 512,  NPIX, CI,  1>;
    cudaFuncSetAttribute(k1a, cudaFuncAttributeMaxDynamicSharedMemorySize, SMEM);
    cudaFuncSetAttribute(k1b, cudaFuncAttributeMaxDynamicSharedMemorySize, SMEM);
    cudaFuncSetAttribute(k2,  cudaFuncAttributeMaxDynamicSharedMemorySize, SMEM);
    cudaFuncSetAttribute(k3,  cudaFuncAttributeMaxDynamicSharedMemorySize, SMEM);
    cudaFuncSetAttribute(k4,  cudaFuncAttributeMaxDynamicSharedMemorySize, SMEM);

    // one prep launch: 4 weight splits + bias stack + stats zero
    prep_splits<<<(4 * 131072) / 256, 256>>>(
        th_w, ph_w, g_w, W_w,
        wtp0, wtp1, gw0, gw1, ww0, ww1,
        th_b, ph_b, tpb, stats);

    // xT 2-level split: (B, 4096, 512), full-width stores
    transpose_split2<<<dim3(NPIX / 32, CCH / 64, BATCH), dim3(32, 8)>>>(x, xt0, xt1);

    // GEMM1a: tp[b](512,4096) = Wtp(512,512) @ xT[b]^T (+ [th_b;ph_b] per row), hi/lo out
    k1a<<<dim3(NPIX / 128, 512 / 64, BATCH), 128, SMEM>>>(
        wtp0, wtp1, xt0, xt1,
        nullptr, tp0, tp1, tpb, nullptr, nullptr,
        0, (long long)NPIX * CCH, 512LL * NPIX);

    // GEMM1b: gT[b](4096,256) = xT[b] @ g_w^T (+ g_b per col), hi/lo out
    k1b<<<dim3(CI / 128, NPIX / 64, BATCH), 128, SMEM>>>(
        xt0, xt1, gw0, gw1,
        nullptr, gt0, gt1, nullptr, g_b, nullptr,
        (long long)NPIX * CCH, 0, (long long)NPIX * CI);

    // GEMM2: f partials = theta @ phi^T, split-K 4, fp32 out
    k2<<<dim3(CI / 128, CI / 64, BATCH * FSPLIT), 128, SMEM>>>(
        tp0, tp1,
        tp0 + (size_t)CI * NPIX, tp1 + (size_t)CI * NPIX,
        fpart, nullptr, nullptr, nullptr, nullptr, nullptr,
        512LL * NPIX, 512LL * NPIX, (long long)CI * CI);

    // softmax (sums FSPLIT partials) -> hi/lo bf16
    softmax_split<<<BATCH * CI, 256>>>(fpart, fs0, fs1);

    // GEMM3: yT[b](4096,256) = gT[b] @ fsm[b]^T, hi/lo out
    k3<<<dim3(CI / 128, NPIX / 64, BATCH), 128, SMEM>>>(
        gt0, gt1, fs0, fs1,
        nullptr, yt0, yt1, nullptr, nullptr, nullptr,
        (long long)NPIX * CI, (long long)CI * CI, (long long)NPIX * CI);

    // GEMM4: z[b](512,4096) = W_w @ yT[b]^T (W_b dropped: cancels in BN),
    //        fp32 out + fused per-channel stats partials
    k4<<<dim3(NPIX / 128, 512 / 64, BATCH), 128, SMEM>>>(
        ww0, ww1, yt0, yt1,
        z, nullptr, nullptr, nullptr, nullptr, stats,
        0, (long long)NPIX * CI, (long long)CCH * NPIX);

    // BN (finalize folded) + residual
    const size_t total4 = (size_t)BATCH * CCH * NPIX / 4;
    bn_residual<<<(unsigned)(total4 / 256), 256>>>(z, x, gamma, beta, stats, out);
}

// round 15
// speedup vs baseline: 1.0001x; 1.0001x over previous
#include <cuda_runtime.h>
#include <cuda_bf16.h>
#include <cstdint>

#define BATCH 16
#define CCH   512
#define CI    256
#define NPIX  4096
#define FSPLIT 4

// ---------------- scratch (device globals; no allocation allowed) ----------------
static const size_t XT_SZ  = (size_t)BATCH * NPIX * CCH;   // per level
static const size_t TP_SZ  = (size_t)BATCH * 512 * NPIX;
static const size_t GT_SZ  = (size_t)BATCH * NPIX * CI;
static const size_t F_SZ   = (size_t)BATCH * CI * CI;
static const size_t YT_SZ  = (size_t)BATCH * NPIX * CI;

__device__ __nv_bfloat16 d_xt [2][(size_t)BATCH * NPIX * CCH];   // 134 MB
__device__ __nv_bfloat16 d_wtp[2][512 * 512];
__device__ __nv_bfloat16 d_gw [2][CI * CCH];
__device__ __nv_bfloat16 d_ww [2][CCH * CI];
__device__ __nv_bfloat16 d_tp [2][(size_t)BATCH * 512 * NPIX];   // 134 MB
__device__ __nv_bfloat16 d_gt [2][(size_t)BATCH * NPIX * CI];    // 67 MB
__device__ float         d_fpart[(size_t)FSPLIT * BATCH * CI * CI]; // 16.8 MB
__device__ __nv_bfloat16 d_fsm[2][(size_t)BATCH * CI * CI];
__device__ __nv_bfloat16 d_yt [2][(size_t)BATCH * NPIX * CI];    // 67 MB
__device__ float         d_z[(size_t)BATCH * CCH * NPIX];        // 134 MB
__device__ float         d_stats[2 * CCH];                       // raw partials
__device__ float         d_tpb[512];

// ---------------- helpers (arch-portable PTX only: sm_80+) ----------------
__device__ __forceinline__ uint32_t smem_u32(const void* p) {
    uint32_t a;
    asm("{ .reg .u64 t; cvta.to.shared.u64 t, %1; cvt.u32.u64 %0, t; }" : "=r"(a) : "l"(p));
    return a;
}

__device__ __forceinline__ void cpasync16(uint32_t dst, const void* src) {
    asm volatile("cp.async.cg.shared.global.L2::256B [%0], [%1], 16;" :: "r"(dst), "l"(src));
}
#define CP_COMMIT() asm volatile("cp.async.commit_group;" ::: "memory")

__device__ __forceinline__ void ldsm4(uint32_t addr, uint32_t& r0, uint32_t& r1,
                                      uint32_t& r2, uint32_t& r3) {
    asm volatile("ldmatrix.sync.aligned.m8n8.x4.shared.b16 {%0,%1,%2,%3}, [%4];"
                 : "=r"(r0), "=r"(r1), "=r"(r2), "=r"(r3) : "r"(addr));
}
__device__ __forceinline__ void mma16816(float* c, const uint32_t* a, uint32_t b0, uint32_t b1) {
    asm volatile(
        "mma.sync.aligned.m16n8k16.row.col.f32.bf16.bf16.f32 "
        "{%0,%1,%2,%3}, {%4,%5,%6,%7}, {%8,%9}, {%0,%1,%2,%3};"
        : "+f"(c[0]), "+f"(c[1]), "+f"(c[2]), "+f"(c[3])
        : "r"(a[0]), "r"(a[1]), "r"(a[2]), "r"(a[3]), "r"(b0), "r"(b1));
}

// =====================================================================
// NT GEMM on tensor cores (mma.sync bf16, fp32 acc), 2-level split inputs:
//   D[M,N] = A0*B0^T + A0*B1^T + A1*B0^T    (ll term dropped, ~2^-18)
// Shapes are TEMPLATE params. A,B: K-major (ld = Kv). CTA tile 64x128,
// 128 threads (4 warps, warp tile 32x64). K-chunk 32 (64B rows, SW64),
// 2-stage cp.async pipeline, ONE __syncthreads per chunk; loads for
// chunk i+1 issued IMMEDIATELY after the sync (other buffer is provably
// free there), giving a full-chunk prefetch window before the next wait.
// 49KB smem -> 4 CTAs/SM.
// MODE: 0 = fp32 out (optional fused stats atomics), 1 = hi/lo bf16 out.
// grid = (Nv/128, Mv/64, batch*NSPLIT)
// =====================================================================
template <int MODE, int Mv, int Nv, int Kv, int NSPLIT>
__global__ __launch_bounds__(128, 4) void mma_nt(
    const __nv_bfloat16* __restrict__ a0, const __nv_bfloat16* __restrict__ a1,
    const __nv_bfloat16* __restrict__ b0, const __nv_bfloat16* __restrict__ b1,
    float* __restrict__ cf,
    __nv_bfloat16* __restrict__ c0, __nv_bfloat16* __restrict__ c1,
    const float* __restrict__ biasRow, const float* __restrict__ biasCol,
    float* __restrict__ statsPart,
    long long sA, long long sB, long long sC)
{
    constexpr int stageBytes = 24576;       // A0 4K | A1 4K | B0 8K | B1 8K
    constexpr int Ksub = Kv / NSPLIT;
    constexpr int nk = Ksub / 32;

    extern __shared__ char smraw[];
    const uint32_t smem_base = (smem_u32(smraw) + 1023u) & ~1023u;

    const int tid = threadIdx.x;
    const int wid = tid >> 5, lid = tid & 31;
    const int warpM = (wid & 1) * 32;       // 2 warps over M (64 rows)
    const int warpN = (wid >> 1) * 64;      // 2 warps over N (128 cols)

    const int bz = blockIdx.z;
    const int b  = bz / NSPLIT, sp = bz % NSPLIT;
    const int k0base = sp * Ksub;
    const int mBase = blockIdx.y * 64;
    const int nBase = blockIdx.x * 128;

    // ---- precomputed cp.async addressing (prologue only) ----
    const int row0 = tid >> 2;              // 0..31
    const int segE = (tid & 3) * 8;
    const __nv_bfloat16* srcA0 = a0 + (size_t)b * sA + (size_t)(mBase + row0) * Kv + k0base + segE;
    const __nv_bfloat16* srcA1 = a1 + (size_t)b * sA + (size_t)(mBase + row0) * Kv + k0base + segE;
    const __nv_bfloat16* srcB0 = b0 + (size_t)b * sB + (size_t)(nBase + row0) * Kv + k0base + segE;
    const __nv_bfloat16* srcB1 = b1 + (size_t)b * sB + (size_t)(nBase + row0) * Kv + k0base + segE;
    uint32_t dstO[4];                       // swizzled dst offsets, tile-local
    #pragma unroll
    for (int c = 0; c < 4; c++) {
        const int row = row0 + 32 * c;
        const uint32_t o = row * 64 + (tid & 3) * 16;
        dstO[c] = o ^ ((row & 6) * 8);      // SW64 swizzle, precomputed
    }

    auto loadChunk = [&](int ci, uint32_t sb) {
        const __nv_bfloat16* s0 = srcA0 + (size_t)ci * 32;
        const __nv_bfloat16* s1 = srcA1 + (size_t)ci * 32;
        const __nv_bfloat16* s2 = srcB0 + (size_t)ci * 32;
        const __nv_bfloat16* s3 = srcB1 + (size_t)ci * 32;
        #pragma unroll
        for (int c = 0; c < 2; c++) {       // A tiles: 64 rows
            cpasync16(sb + dstO[c],         s0 + (size_t)c * 32 * Kv);
            cpasync16(sb + 4096 + dstO[c],  s1 + (size_t)c * 32 * Kv);
        }
        #pragma unroll
        for (int c = 0; c < 4; c++) {       // B tiles: 128 rows
            cpasync16(sb + 8192 + dstO[c],  s2 + (size_t)c * 32 * Kv);
            cpasync16(sb + 16384 + dstO[c], s3 + (size_t)c * 32 * Kv);
        }
    };

    float acc[2][8][4];
    #pragma unroll
    for (int i = 0; i < 2; i++)
        #pragma unroll
        for (int j = 0; j < 8; j++)
            #pragma unroll
            for (int k = 0; k < 4; k++) acc[i][j][k] = 0.f;

    loadChunk(0, smem_base); CP_COMMIT();

    const int lRow = lid & 15;
    const uint32_t colH = ((lid >> 4) & 1) * 16;

    // precomputed FULL ldsm offsets (stage-relative): 1 ADD per LDSM at use
    uint32_t offA[2][2], offB[2][4];        // [ks][site]
    #pragma unroll
    for (int mi = 0; mi < 2; mi++) {
        const int row = warpM + 16 * mi + lRow;
        const uint32_t ba = row * 64, xr = (row & 6) * 8;
        offA[0][mi] = ba + (colH ^ xr);
        offA[1][mi] = ba + ((32 + colH) ^ xr);
    }
    #pragma unroll
    for (int nj = 0; nj < 4; nj++) {
        const int row = warpN + 16 * nj + lRow;
        const uint32_t ba = row * 64, xr = (row & 6) * 8;
        offB[0][nj] = ba + (colH ^ xr);
        offB[1][nj] = ba + ((32 + colH) ^ xr);
    }

// One ks-step: product order A0B0 -> (load fb1) A0B1 -> (load fa1) A1B0.
// Peak live frags: fa0(8)+fb0(16)+fb1(16)=40 regs.
#define COMPUTE_KS(KS)                                                          \
    {                                                                           \
        uint32_t fa0[2][4], fb0[4][4];                                          \
        _Pragma("unroll")                                                       \
        for (int mi = 0; mi < 2; mi++)                                          \
            ldsm4(A0b + offA[KS][mi],                                           \
                  fa0[mi][0], fa0[mi][1], fa0[mi][2], fa0[mi][3]);              \
        _Pragma("unroll")                                                       \
        for (int nj = 0; nj < 4; nj++)                                          \
            ldsm4(B0b + offB[KS][nj],                                           \
                  fb0[nj][0], fb0[nj][1], fb0[nj][2], fb0[nj][3]);              \
        _Pragma("unroll")                                                       \
        for (int mi = 0; mi < 2; mi++)                                          \
            _Pragma("unroll")                                                   \
            for (int jn = 0; jn < 8; jn++)                                      \
                mma16816(acc[mi][jn], fa0[mi],                                  \
                         fb0[jn >> 1][jn & 1], fb0[jn >> 1][2 + (jn & 1)]);     \
        {                                                                       \
            uint32_t fb1[4][4];                                                 \
            _Pragma("unroll")                                                   \
            for (int nj = 0; nj < 4; nj++)                                      \
                ldsm4(B1b + offB[KS][nj],                                       \
                      fb1[nj][0], fb1[nj][1], fb1[nj][2], fb1[nj][3]);          \
            _Pragma("unroll")                                                   \
            for (int mi = 0; mi < 2; mi++)                                      \
                _Pragma("unroll")                                               \
                for (int jn = 0; jn < 8; jn++)                                  \
                    mma16816(acc[mi][jn], fa0[mi],                              \
                             fb1[jn >> 1][jn & 1], fb1[jn >> 1][2 + (jn & 1)]); \
        }                                                                       \
        {                                                                       \
            uint32_t fa1[2][4];                                                 \
            _Pragma("unroll")                                                   \
            for (int mi = 0; mi < 2; mi++)                                      \
                ldsm4(A1b + offA[KS][mi],                                       \
                      fa1[mi][0], fa1[mi][1], fa1[mi][2], fa1[mi][3]);          \
            _Pragma("unroll")                                                   \
            for (int mi = 0; mi < 2; mi++)                                      \
                _Pragma("unroll")                                               \
                for (int jn = 0; jn < 8; jn++)                                  \
                    mma16816(acc[mi][jn], fa1[mi],                              \
                             fb0[jn >> 1][jn & 1], fb0[jn >> 1][2 + (jn & 1)]); \
        }                                                                       \
    }

    #pragma unroll 1
    for (int i = 0; i < nk; i++) {
        const uint32_t sb = smem_base + (i & 1) * stageBytes;
        asm volatile("cp.async.wait_group 0;" ::: "memory");   // chunk i arrived
        __syncthreads();   // + all warps done reading the OTHER buffer (chunk i-1)

        // issue next chunk's loads NOW: other buffer is free, and the loads get
        // a full chunk of compute to land before the next wait_group.
        if (i + 1 < nk) {
            loadChunk(i + 1, smem_base + ((i + 1) & 1) * stageBytes);
            CP_COMMIT();
        }

        const uint32_t A0b = sb, A1b = sb + 4096;
        const uint32_t B0b = sb + 8192, B1b = sb + 16384;

        COMPUTE_KS(0);
        COMPUTE_KS(1);
    }
#undef COMPUTE_KS

    // ---- epilogue ----
    const int gr = lid >> 2;            // 0..7
    const int gc = (lid & 3) * 2;       // 0,2,4,6
    const size_t cOff = (size_t)bz * sC;

    #pragma unroll
    for (int mi = 0; mi < 2; mi++) {
        const int row0e = mBase + warpM + 16 * mi + gr;
        const int row1e = row0e + 8;
        const float br0 = biasRow ? biasRow[row0e] : 0.f;
        const float br1 = biasRow ? biasRow[row1e] : 0.f;
        float s0 = 0.f, q0 = 0.f, s1 = 0.f, q1 = 0.f;
        #pragma unroll
        for (int jn = 0; jn < 8; jn++) {
            const int col = nBase + warpN + 8 * jn + gc;
            float v00 = acc[mi][jn][0] + br0;
            float v01 = acc[mi][jn][1] + br0;
            float v10 = acc[mi][jn][2] + br1;
            float v11 = acc[mi][jn][3] + br1;
            if (biasCol) {
                const float bc0 = biasCol[col], bc1 = biasCol[col + 1];
                v00 += bc0; v01 += bc1; v10 += bc0; v11 += bc1;
            }
            const size_t base0 = cOff + (size_t)row0e * Nv + col;
            const size_t base1 = cOff + (size_t)row1e * Nv + col;
            if (MODE == 0) {
                *(float2*)(cf + base0) = make_float2(v00, v01);
                *(float2*)(cf + base1) = make_float2(v10, v11);
                if (statsPart) {
                    s0 += v00 + v01; q0 += v00 * v00 + v01 * v01;
                    s1 += v10 + v11; q1 += v10 * v10 + v11 * v11;
                }
            } else {
                float vv[2][2] = {{v00, v01}, {v10, v11}};
                const size_t bb[2] = {base0, base1};
                #pragma unroll
                for (int r = 0; r < 2; r++) {
                    __nv_bfloat16 h0 = __float2bfloat16(vv[r][0]);
                    __nv_bfloat16 h1 = __float2bfloat16(vv[r][1]);
                    float r0 = vv[r][0] - __bfloat162float(h0);
                    float r1 = vv[r][1] - __bfloat162float(h1);
                    __nv_bfloat162 th; th.x = h0; th.y = h1;
                    __nv_bfloat162 tl;
                    tl.x = __float2bfloat16(r0); tl.y = __float2bfloat16(r1);
                    *(__nv_bfloat162*)(c0 + bb[r]) = th;
                    *(__nv_bfloat162*)(c1 + bb[r]) = tl;
                }
            }
        }
        if (MODE == 0 && statsPart) {
            #pragma unroll
            for (int o = 1; o < 4; o <<= 1) {
                s0 += __shfl_xor_sync(0xFFFFFFFFu, s0, o);
                q0 += __shfl_xor_sync(0xFFFFFFFFu, q0, o);
                s1 += __shfl_xor_sync(0xFFFFFFFFu, s1, o);
                q1 += __shfl_xor_sync(0xFFFFFFFFu, q1, o);
            }
            if ((lid & 3) == 0) {
                atomicAdd(&statsPart[row0e], s0);
                atomicAdd(&statsPart[CCH + row0e], q0);
                atomicAdd(&statsPart[row1e], s1);
                atomicAdd(&statsPart[CCH + row1e], q1);
            }
        }
    }
}

// =====================================================================
// prep: all four weight splits + bias stack + stats zero (ONE launch)
// =====================================================================
__global__ void prep_splits(
    const float* __restrict__ th_w, const float* __restrict__ ph_w,
    const float* __restrict__ g_w,  const float* __restrict__ W_w,
    __nv_bfloat16* __restrict__ wtp0, __nv_bfloat16* __restrict__ wtp1,
    __nv_bfloat16* __restrict__ gw0,  __nv_bfloat16* __restrict__ gw1,
    __nv_bfloat16* __restrict__ ww0,  __nv_bfloat16* __restrict__ ww1,
    const float* __restrict__ th_b, const float* __restrict__ ph_b,
    float* __restrict__ tpb, float* __restrict__ stats)
{
    const int i = blockIdx.x * 256 + threadIdx.x;   // 0 .. 4*131072-1
    const int arr = i >> 17;
    const int off = i & 131071;
    const float* src;
    __nv_bfloat16 *dh, *dl;
    switch (arr) {
        case 0:  src = th_w; dh = wtp0;          dl = wtp1;          break;
        case 1:  src = ph_w; dh = wtp0 + 131072; dl = wtp1 + 131072; break;
        case 2:  src = g_w;  dh = gw0;           dl = gw1;           break;
        default: src = W_w;  dh = ww0;           dl = ww1;           break;
    }
    const float v = src[off];
    const __nv_bfloat16 hh = __float2bfloat16(v);
    dh[off] = hh;
    dl[off] = __float2bfloat16(v - __bfloat162float(hh));

    if (i < 512)  tpb[i]  = (i < 256) ? th_b[i] : ph_b[i - 256];
    if (i < 1024) stats[i] = 0.f;
}

// =====================================================================
// transpose + 2-level split of x: 32n x 64c tiles, full-width bf16x2 stores
// =====================================================================
__global__ void transpose_split2(const float* __restrict__ x,
                                 __nv_bfloat16* __restrict__ h,
                                 __nv_bfloat16* __restrict__ l)
{
    __shared__ float t[64][33];
    const int b = blockIdx.z;
    const int n0 = blockIdx.x * 32, c0 = blockIdx.y * 64;
    const float* xb = x + (size_t)b * CCH * NPIX;
    #pragma unroll
    for (int k = 0; k < 8; k++) {
        const int cl = threadIdx.y + k * 8;
        t[cl][threadIdx.x] = xb[(size_t)(c0 + cl) * NPIX + n0 + threadIdx.x];
    }
    __syncthreads();
    const size_t ob = (size_t)b * NPIX * CCH;
    #pragma unroll
    for (int k = 0; k < 4; k++) {
        const int nl = threadIdx.y + k * 8;
        const float v0 = t[2 * threadIdx.x][nl];
        const float v1 = t[2 * threadIdx.x + 1][nl];
        const __nv_bfloat16 h0 = __float2bfloat16(v0);
        const __nv_bfloat16 h1 = __float2bfloat16(v1);
        __nv_bfloat162 th; th.x = h0; th.y = h1;
        __nv_bfloat162 tl;
        tl.x = __float2bfloat16(v0 - __bfloat162float(h0));
        tl.y = __float2bfloat16(v1 - __bfloat162float(h1));
        const size_t idx = ob + (size_t)(n0 + nl) * CCH + c0 + 2 * threadIdx.x;
        *(__nv_bfloat162*)(h + idx) = th;
        *(__nv_bfloat162*)(l + idx) = tl;
    }
}

__global__ __launch_bounds__(256) void softmax_split(
    const float* __restrict__ fp, __nv_bfloat16* __restrict__ h, __nv_bfloat16* __restrict__ l)
{
    const int row = blockIdx.x;        // b*256 + c
    const int b = row >> 8, c = row & 255;
    const int d = threadIdx.x;
    float v = 0.f;
    #pragma unroll
    for (int s = 0; s < FSPLIT; s++)
        v += fp[((size_t)(b * FSPLIT + s)) * (CI * CI) + c * CI + d];
    __shared__ float red[256];
    red[d] = v; __syncthreads();
    for (int o = 128; o > 0; o >>= 1) {
        if (d < o) red[d] = fmaxf(red[d], red[d + o]);
        __syncthreads();
    }
    const float mx = red[0];
    __syncthreads();
    const float e = __expf(v - mx);
    red[d] = e; __syncthreads();
    for (int o = 128; o > 0; o >>= 1) {
        if (d < o) red[d] += red[d + o];
        __syncthreads();
    }
    const float p = e / red[0];
    const size_t idx = (size_t)row * CI + d;
    __nv_bfloat16 hh = __float2bfloat16(p);
    h[idx] = hh; l[idx] = __float2bfloat16(p - __bfloat162float(hh));
}

// =====================================================================
// BN (finalize folded in) + residual
// =====================================================================
__global__ __launch_bounds__(256) void bn_residual(
    const float* __restrict__ z, const float* __restrict__ x,
    const float* __restrict__ gamma, const float* __restrict__ beta,
    const float* __restrict__ stats, float* __restrict__ out)
{
    const size_t i = (size_t)blockIdx.x * blockDim.x + threadIdx.x;
    const int c = (int)((i >> 10) & (CCH - 1));
    const float cnt = (float)(BATCH * NPIX);
    const float m = stats[c] / cnt;
    const float var = stats[CCH + c] / cnt - m * m;
    const float r = rsqrtf(var + 1e-5f);
    const float g = gamma[c], bb = beta[c];
    const float4 zv = ((const float4*)z)[i];
    const float4 xv = ((const float4*)x)[i];
    float4 o;
    o.x = (zv.x - m) * r * g + bb + xv.x;
    o.y = (zv.y - m) * r * g + bb + xv.y;
    o.z = (zv.z - m) * r * g + bb + xv.z;
    o.w = (zv.w - m) * r * g + bb + xv.w;
    ((float4*)out)[i] = o;
}

// =====================================================================
// launch
// =====================================================================
extern "C" void kernel_launch(void* const* d_in, const int* in_sizes, int n_in,
                              void* d_out, int out_size)
{
    (void)in_sizes; (void)n_in; (void)out_size;
    const float* x     = (const float*)d_in[0];
    const float* g_w   = (const float*)d_in[1];
    const float* g_b   = (const float*)d_in[2];
    const float* th_w  = (const float*)d_in[3];
    const float* th_b  = (const float*)d_in[4];
    const float* ph_w  = (const float*)d_in[5];
    const float* ph_b  = (const float*)d_in[6];
    const float* W_w   = (const float*)d_in[7];
    const float* gamma = (const float*)d_in[9];
    const float* beta  = (const float*)d_in[10];
    float* out = (float*)d_out;

    __nv_bfloat16 *xt, *wtp, *gw, *ww, *tp, *gt, *fsm, *yt;
    float *fpart, *z, *stats, *tpb;
    cudaGetSymbolAddress((void**)&xt,    d_xt);
    cudaGetSymbolAddress((void**)&wtp,   d_wtp);
    cudaGetSymbolAddress((void**)&gw,    d_gw);
    cudaGetSymbolAddress((void**)&ww,    d_ww);
    cudaGetSymbolAddress((void**)&tp,    d_tp);
    cudaGetSymbolAddress((void**)&gt,    d_gt);
    cudaGetSymbolAddress((void**)&fpart, d_fpart);
    cudaGetSymbolAddress((void**)&fsm,   d_fsm);
    cudaGetSymbolAddress((void**)&yt,    d_yt);
    cudaGetSymbolAddress((void**)&z,     d_z);
    cudaGetSymbolAddress((void**)&stats, d_stats);
    cudaGetSymbolAddress((void**)&tpb,   d_tpb);

    __nv_bfloat16 *xt0 = xt, *xt1 = xt + XT_SZ;
    __nv_bfloat16 *wtp0 = wtp, *wtp1 = wtp + 512 * 512;
    __nv_bfloat16 *gw0 = gw, *gw1 = gw + CI * CCH;
    __nv_bfloat16 *ww0 = ww, *ww1 = ww + CCH * CI;
    __nv_bfloat16 *tp0 = tp, *tp1 = tp + TP_SZ;
    __nv_bfloat16 *gt0 = gt, *gt1 = gt + GT_SZ;
    __nv_bfloat16 *fs0 = fsm, *fs1 = fsm + F_SZ;
    __nv_bfloat16 *yt0 = yt, *yt1 = yt + YT_SZ;

    const int SMEM = 2 * 24576 + 1024;   // 2-stage, K-chunk 32: 50176 B -> 4 CTAs/SM

    auto* k1a = mma_nt<1, 512,  NPIX, CCH, 1>;
    auto* k1b = mma_nt<1, NPIX, CI,   CCH, 1>;
    auto* k2  = mma_nt<0, CI,   CI,   NPIX, FSPLIT>;
    auto* k3  = mma_nt<1, NPIX, CI,   CI,  1>;
    auto* k4  = mma_nt<0, 512,  NPIX, CI,  1>;
    cudaFuncSetAttribute(k1a, cudaFuncAttributeMaxDynamicSharedMemorySize, SMEM);
    cudaFuncSetAttribute(k1b, cudaFuncAttributeMaxDynamicSharedMemorySize, SMEM);
    cudaFuncSetAttribute(k2,  cudaFuncAttributeMaxDynamicSharedMemorySize, SMEM);
    cudaFuncSetAttribute(k3,  cudaFuncAttributeMaxDynamicSharedMemorySize, SMEM);
    cudaFuncSetAttribute(k4,  cudaFuncAttributeMaxDynamicSharedMemorySize, SMEM);

    // one prep launch: 4 weight splits + bias stack + stats zero
    prep_splits<<<(4 * 131072) / 256, 256>>>(
        th_w, ph_w, g_w, W_w,
        wtp0, wtp1, gw0, gw1, ww0, ww1,
        th_b, ph_b, tpb, stats);

    // xT 2-level split: (B, 4096, 512)
    transpose_split2<<<dim3(NPIX / 32, CCH / 64, BATCH), dim3(32, 8)>>>(x, xt0, xt1);

    // GEMM1a: tp[b](512,4096) = Wtp(512,512) @ xT[b]^T (+ [th_b;ph_b] per row), hi/lo out
    k1a<<<dim3(NPIX / 128, 512 / 64, BATCH), 128, SMEM>>>(
        wtp0, wtp1, xt0, xt1,
        nullptr, tp0, tp1, tpb, nullptr, nullptr,
        0, (long long)NPIX * CCH, 512LL * NPIX);

    // GEMM1b: gT[b](4096,256) = xT[b] @ g_w^T (+ g_b per col), hi/lo out
    k1b<<<dim3(CI / 128, NPIX / 64, BATCH), 128, SMEM>>>(
        xt0, xt1, gw0, gw1,
        nullptr, gt0, gt1, nullptr, g_b, nullptr,
        (long long)NPIX * CCH, 0, (long long)NPIX * CI);

    // GEMM2: f partials = theta @ phi^T, split-K 4, fp32 out
    k2<<<dim3(CI / 128, CI / 64, BATCH * FSPLIT), 128, SMEM>>>(
        tp0, tp1,
        tp0 + (size_t)CI * NPIX, tp1 + (size_t)CI * NPIX,
        fpart, nullptr, nullptr, nullptr, nullptr, nullptr,
        512LL * NPIX, 512LL * NPIX, (long long)CI * CI);

    // softmax (sums FSPLIT partials) -> hi/lo bf16
    softmax_split<<<BATCH * CI, 256>>>(fpart, fs0, fs1);

    // GEMM3: yT[b](4096,256) = gT[b] @ fsm[b]^T, hi/lo out
    k3<<<dim3(CI / 128, NPIX / 64, BATCH), 128, SMEM>>>(
        gt0, gt1, fs0, fs1,
        nullptr, yt0, yt1, nullptr, nullptr, nullptr,
        (long long)NPIX * CI, (long long)CI * CI, (long long)NPIX * CI);

    // GEMM4: z[b](512,4096) = W_w @ yT[b]^T (W_b dropped: cancels in BN),
    //        fp32 out + fused per-channel stats partials
    k4<<<dim3(NPIX / 128, 512 / 64, BATCH), 128, SMEM>>>(
        ww0, ww1, yt0, yt1,
        z, nullptr, nullptr, nullptr, nullptr, stats,
        0, (long long)NPIX * CI, (long long)CCH * NPIX);

    // BN (finalize folded) + residual
    const size_t total4 = (size_t)BATCH * CCH * NPIX / 4;
    bn_residual<<<(unsigned)(total4 / 256), 256>>>(z, x, gamma, beta, stats, out);
}